// round 2
// baseline (speedup 1.0000x reference)
#include <cuda_runtime.h>

// CASSI forward: out[b,l,i,j] = phi[i,j] * y2[b,i,2l+j]
// y2[b,i,k] = sum_{l'} x[b,l',i,k-2l'] * phi[i,k-2l']  (0 <= k-2l' < N)
//
// Shapes: x (B=8, L=28, M=512, N=512) f32, phi (512,512) f32, out same as x.
// One CTA per (b, i) row. Everything float2-vectorized; parity of STRIDE=2
// guarantees pairs never straddle the [0,N) boundary.

#define B_      8
#define L_      28
#define M_      512
#define N_      512
#define STRIDE_ 2
#define NOUT_   (N_ + STRIDE_ * (L_ - 1))   // 566
#define TPB     256
#define TAIL2_  ((NOUT_ - N_) / 2)          // 27 float2 tail slots

__global__ __launch_bounds__(TPB) void cassi_fused_kernel(
    const float* __restrict__ x,
    const float* __restrict__ phi,
    float* __restrict__ out)
{
    __shared__ float  phi_s[N_];
    __shared__ float2 y2_s[NOUT_ / 2 + 1];  // 284 float2 = 568 floats

    const int bm  = blockIdx.x;      // 0 .. B*M-1
    const int b   = bm / M_;
    const int i   = bm % M_;
    const int t   = threadIdx.x;

    // ---- load phi row i into smem (float4) ----
    {
        const float4* p4 = reinterpret_cast<const float4*>(phi + (size_t)i * N_);
        if (t < N_ / 4)
            reinterpret_cast<float4*>(phi_s)[t] = p4[t];
    }
    __syncthreads();

    // phi pair for this thread's output columns j = 2t, 2t+1 (epilogue)
    const float2 phi_reg = reinterpret_cast<const float2*>(phi_s)[t];

    const float* xb = x + (size_t)b * (L_ * M_ * N_) + (size_t)i * N_;
    const size_t band_stride = (size_t)M_ * N_;

    // ---- main loop: thread t accumulates y2 pair k = {2t, 2t+1},
    //      plus tail pair k = {512+2t, 513+2t} for t < 27 ----
    float2 acc_a = make_float2(0.f, 0.f);
    float2 acc_b = make_float2(0.f, 0.f);

    #pragma unroll
    for (int l = 0; l < L_; ++l) {
        const float* xrow = xb + (size_t)l * band_stride;

        const int n = 2 * t - 2 * l;                 // even, pair-safe
        if ((unsigned)n < N_) {
            float2 xv = *reinterpret_cast<const float2*>(xrow + n);
            float2 pv = *reinterpret_cast<const float2*>(phi_s + n);
            acc_a.x += xv.x * pv.x;
            acc_a.y += xv.y * pv.y;
        }

        if (t < TAIL2_ && l > t) {                   // n2 = 512+2t-2l in [0,512)
            const int n2 = N_ + 2 * t - 2 * l;
            float2 xv = *reinterpret_cast<const float2*>(xrow + n2);
            float2 pv = *reinterpret_cast<const float2*>(phi_s + n2);
            acc_b.x += xv.x * pv.x;
            acc_b.y += xv.y * pv.y;
        }
    }

    y2_s[t] = acc_a;                                 // words 2t, 2t+1
    if (t < TAIL2_)
        y2_s[N_ / 2 + t] = acc_b;                    // words 512+2t, 513+2t
    __syncthreads();

    // ---- epilogue: out[b,l,i,2t..2t+1] = phi_reg * y2[2l + 2t .. +1]
    //      y2 word offset 2l+2t == float2 index (l+t): conflict-free LDS.64 ----
    float* ob = out + (size_t)b * (L_ * M_ * N_) + (size_t)i * N_ + 2 * t;

    #pragma unroll
    for (int l = 0; l < L_; ++l) {
        float2 yv = y2_s[l + t];
        float2 r;
        r.x = phi_reg.x * yv.x;
        r.y = phi_reg.y * yv.y;
        *reinterpret_cast<float2*>(ob + (size_t)l * band_stride) = r;
    }
}

extern "C" void kernel_launch(void* const* d_in, const int* in_sizes, int n_in,
                              void* d_out, int out_size)
{
    const float* x   = (const float*)d_in[0];
    const float* phi = (const float*)d_in[1];
    float* out       = (float*)d_out;

    cassi_fused_kernel<<<B_ * M_, TPB>>>(x, phi, out);
}